// round 5
// baseline (speedup 1.0000x reference)
#include <cuda_runtime.h>
#include <cuda_fp16.h>
#include <cstdint>

#define N_NODES 100000
#define N_EDGES 3200000
#define D_IN    128
#define D_OUT   64
#define CAP     96      // max in-degree bucket capacity (actual max ~58 for Poisson(32))

// ---------------- scratch (static device globals; no allocation) ----------------
__device__ float g_z   [(size_t)N_NODES * D_OUT];   // 25.6 MB projected features (fp32)
__device__ float g_zs  [N_NODES];                   // z . a[:64]
__device__ float g_zd  [N_NODES];                   // z . a[64:]
__device__ int   g_cnt [N_NODES];                   // bucket fill counts
__device__ int2  g_perm[(size_t)N_NODES * CAP];     // (src, bitcast(w)) buckets, 76.8 MB

// ---------------- K0: zero counts ----------------
__global__ void k_zero() {
    int i = blockIdx.x * blockDim.x + threadIdx.x;
    if (i < N_NODES) g_cnt[i] = 0;
}

// ---------------- K1: z = h @ W  (+ fused zs/zd epilogue) ----------------
// block = 256 threads; tile = 32 nodes x 64 cols; thread = 2 nodes x 4 cols.
__global__ __launch_bounds__(256) void k_gemm(const float* __restrict__ h,
                                              const float* __restrict__ W,
                                              const float* __restrict__ a) {
    __shared__ float sW[D_IN][D_OUT];   // 32 KB
    __shared__ float sh[32][D_IN];      // 16 KB

    int t = threadIdx.x;
    {
        const float4* W4 = (const float4*)W;
        float4* sW4 = (float4*)sW;
        #pragma unroll
        for (int i = 0; i < 8; ++i) sW4[t + i * 256] = W4[t + i * 256];
    }
    {
        int n0 = blockIdx.x * 32;
        const float4* h4 = (const float4*)(h + (size_t)n0 * D_IN);
        float4* sh4 = (float4*)sh;
        #pragma unroll
        for (int i = 0; i < 4; ++i) sh4[t + i * 256] = h4[t + i * 256];
    }
    __syncthreads();

    int tx = t & 15;          // column group: cols c0..c0+3
    int ty = t >> 4;          // node group:   rows r0, r0+1
    int c0 = tx * 4;
    int r0 = ty * 2;

    float acc[2][4] = {};
    #pragma unroll
    for (int k = 0; k < D_IN; k += 4) {
        float4 w0 = *(const float4*)&sW[k + 0][c0];
        float4 w1 = *(const float4*)&sW[k + 1][c0];
        float4 w2 = *(const float4*)&sW[k + 2][c0];
        float4 w3 = *(const float4*)&sW[k + 3][c0];
        #pragma unroll
        for (int r = 0; r < 2; ++r) {
            float4 hv = *(const float4*)&sh[r0 + r][k];
            acc[r][0] = fmaf(hv.x, w0.x, fmaf(hv.y, w1.x, fmaf(hv.z, w2.x, fmaf(hv.w, w3.x, acc[r][0]))));
            acc[r][1] = fmaf(hv.x, w0.y, fmaf(hv.y, w1.y, fmaf(hv.z, w2.y, fmaf(hv.w, w3.y, acc[r][1]))));
            acc[r][2] = fmaf(hv.x, w0.z, fmaf(hv.y, w1.z, fmaf(hv.z, w2.z, fmaf(hv.w, w3.z, acc[r][2]))));
            acc[r][3] = fmaf(hv.x, w0.w, fmaf(hv.y, w1.w, fmaf(hv.z, w2.w, fmaf(hv.w, w3.w, acc[r][3]))));
        }
    }

    int n0 = blockIdx.x * 32;
    float4 as = *(const float4*)&a[c0];
    float4 ad = *(const float4*)&a[64 + c0];

    #pragma unroll
    for (int r = 0; r < 2; ++r) {
        int n = n0 + r0 + r;
        float4 zv = make_float4(acc[r][0], acc[r][1], acc[r][2], acc[r][3]);
        *(float4*)&g_z[(size_t)n * D_OUT + c0] = zv;
        float zs = acc[r][0] * as.x + acc[r][1] * as.y + acc[r][2] * as.z + acc[r][3] * as.w;
        float zd = acc[r][0] * ad.x + acc[r][1] * ad.y + acc[r][2] * ad.z + acc[r][3] * ad.w;
        #pragma unroll
        for (int o = 8; o > 0; o >>= 1) {
            zs += __shfl_xor_sync(0xffffffffu, zs, o);
            zd += __shfl_xor_sync(0xffffffffu, zd, o);
        }
        if (tx == 0) { g_zs[n] = zs; g_zd[n] = zd; }
    }
}

// ---------------- K2: edge pass (2 edges/thread): w = exp(e), drop into dst bucket ----
__global__ void k_edge(const int* __restrict__ src, const int* __restrict__ dst) {
    int i = blockIdx.x * blockDim.x + threadIdx.x;   // edge pair index
    if (i * 2 >= N_EDGES) return;
    int2 s2 = ((const int2*)src)[i];
    int2 d2 = ((const int2*)dst)[i];
    float w0 = __expf(g_zs[s2.x] + g_zd[d2.x]);      // max-shift unnecessary (|e| < ~6)
    int p0 = atomicAdd(&g_cnt[d2.x], 1);
    g_perm[d2.x * CAP + p0] = make_int2(s2.x, __float_as_int(w0));
    float w1 = __expf(g_zs[s2.y] + g_zd[d2.y]);
    int p1 = atomicAdd(&g_cnt[d2.y], 1);
    g_perm[d2.y * CAP + p1] = make_int2(s2.y, __float_as_int(w1));
}

// ---------------- K3: warp-per-node accumulate, 2 edges per step, fp32 z ----------
// Warp splits into two 16-lane halves; each half handles one edge, loading the
// full 256B fp32 z-row as 16 x float4 (LDG.128). Bucket pairs come in as one
// broadcast int4 per warp. Cross-half combine via shfl. No converts anywhere.
__global__ __launch_bounds__(256) void k_accum(float* __restrict__ out) {
    int gw   = (blockIdx.x * 256 + threadIdx.x) >> 5;
    int lane = threadIdx.x & 31;
    if (gw >= N_NODES) return;
    int cnt  = g_cnt[gw];
    const int2* bucket = g_perm + (size_t)gw * CAP;
    int half = lane >> 4;       // which edge of the pair
    int cg   = lane & 15;       // column group: cols 4*cg .. 4*cg+3
    const float4* zrow = (const float4*)g_z;   // 16 float4 per node row

    float acc0 = 0.0f, acc1 = 0.0f, acc2 = 0.0f, acc3 = 0.0f, den = 0.0f;
    int j = 0;
    #pragma unroll 1
    for (; j + 4 <= cnt; j += 4) {
        int4 b0 = *(const int4*)&bucket[j];        // edges j, j+1
        int4 b1 = *(const int4*)&bucket[j + 2];    // edges j+2, j+3
        int   s0 = half ? b0.z : b0.x;
        float w0 = __int_as_float(half ? b0.w : b0.y);
        int   s1 = half ? b1.z : b1.x;
        float w1 = __int_as_float(half ? b1.w : b1.y);
        float4 z0 = zrow[s0 * 16 + cg];
        float4 z1 = zrow[s1 * 16 + cg];
        acc0 = fmaf(w0, z0.x, acc0); acc1 = fmaf(w0, z0.y, acc1);
        acc2 = fmaf(w0, z0.z, acc2); acc3 = fmaf(w0, z0.w, acc3);
        acc0 = fmaf(w1, z1.x, acc0); acc1 = fmaf(w1, z1.y, acc1);
        acc2 = fmaf(w1, z1.z, acc2); acc3 = fmaf(w1, z1.w, acc3);
        den += w0 + w1;
    }
    for (; j < cnt; j += 2) {
        int4 b = *(const int4*)&bucket[j];         // CAP even -> in-bounds read
        int   s = half ? b.z : b.x;
        float w = __int_as_float(half ? b.w : b.y);
        if (j + half >= cnt) { s = 0; w = 0.0f; }
        float4 zv = zrow[s * 16 + cg];
        acc0 = fmaf(w, zv.x, acc0); acc1 = fmaf(w, zv.y, acc1);
        acc2 = fmaf(w, zv.z, acc2); acc3 = fmaf(w, zv.w, acc3);
        den += w;
    }
    acc0 += __shfl_xor_sync(0xffffffffu, acc0, 16);
    acc1 += __shfl_xor_sync(0xffffffffu, acc1, 16);
    acc2 += __shfl_xor_sync(0xffffffffu, acc2, 16);
    acc3 += __shfl_xor_sync(0xffffffffu, acc3, 16);
    den  += __shfl_xor_sync(0xffffffffu, den,  16);
    float inv = (cnt > 0) ? (1.0f / den) : 0.0f;
    if (half == 0) {
        float4 r = make_float4(acc0 * inv, acc1 * inv, acc2 * inv, acc3 * inv);
        ((float4*)out)[(size_t)gw * 16 + cg] = r;
    }
}

// ---------------- launch ----------------
extern "C" void kernel_launch(void* const* d_in, const int* in_sizes, int n_in,
                              void* d_out, int out_size) {
    const float* h   = (const float*)d_in[0];
    const float* W   = (const float*)d_in[1];
    const float* a   = (const float*)d_in[2];
    const int*   src = (const int*)d_in[3];
    const int*   dst = (const int*)d_in[4];
    float* out = (float*)d_out;
    (void)in_sizes; (void)n_in; (void)out_size;

    k_zero<<<(N_NODES + 255) / 256, 256>>>();
    k_gemm<<<N_NODES / 32, 256>>>(h, W, a);                    // 100000 % 32 == 0
    k_edge<<<((N_EDGES / 2) + 255) / 256, 256>>>(src, dst);    // 2 edges / thread
    k_accum<<<(N_NODES * 32 + 255) / 256, 256>>>(out);
}

// round 6
// speedup vs baseline: 1.0031x; 1.0031x over previous
#include <cuda_runtime.h>
#include <cuda_fp16.h>
#include <cstdint>

#define N_NODES 100000
#define N_EDGES 3200000
#define D_IN    128
#define D_OUT   64
#define CAP     96      // max in-degree bucket capacity (actual max ~58 for Poisson(32))

// ---------------- scratch (static device globals; no allocation) ----------------
__device__ unsigned g_zh  [(size_t)N_NODES * 32];      // z as half2 (64 cols -> 32 words), 12.8 MB
__device__ float    g_zs  [N_NODES];                   // z . a[:64]
__device__ float    g_zd  [N_NODES];                   // z . a[64:]
__device__ int      g_cnt [N_NODES];                   // bucket fill counts
__device__ int2     g_perm[(size_t)N_NODES * CAP];     // (src, bitcast(w)) buckets, 76.8 MB

// ---------------- K0: zero counts ----------------
__global__ void k_zero() {
    int i = blockIdx.x * blockDim.x + threadIdx.x;
    if (i < N_NODES) g_cnt[i] = 0;
}

// ---------------- K1: z = h @ W  (+ fused zs/zd epilogue, fp16 z store) ----------------
// block = 256 threads; tile = 32 nodes x 64 cols; thread = 2 nodes x 4 cols.
__global__ __launch_bounds__(256) void k_gemm(const float* __restrict__ h,
                                              const float* __restrict__ W,
                                              const float* __restrict__ a) {
    __shared__ float sW[D_IN][D_OUT];   // 32 KB
    __shared__ float sh[32][D_IN];      // 16 KB

    int t = threadIdx.x;
    {
        const float4* W4 = (const float4*)W;
        float4* sW4 = (float4*)sW;
        #pragma unroll
        for (int i = 0; i < 8; ++i) sW4[t + i * 256] = W4[t + i * 256];
    }
    {
        int n0 = blockIdx.x * 32;
        const float4* h4 = (const float4*)(h + (size_t)n0 * D_IN);
        float4* sh4 = (float4*)sh;
        #pragma unroll
        for (int i = 0; i < 4; ++i) sh4[t + i * 256] = h4[t + i * 256];
    }
    __syncthreads();

    int tx = t & 15;          // column group: cols c0..c0+3
    int ty = t >> 4;          // node group:   rows r0, r0+1
    int c0 = tx * 4;
    int r0 = ty * 2;

    float acc[2][4] = {};
    #pragma unroll
    for (int k = 0; k < D_IN; k += 4) {
        float4 w0 = *(const float4*)&sW[k + 0][c0];
        float4 w1 = *(const float4*)&sW[k + 1][c0];
        float4 w2 = *(const float4*)&sW[k + 2][c0];
        float4 w3 = *(const float4*)&sW[k + 3][c0];
        #pragma unroll
        for (int r = 0; r < 2; ++r) {
            float4 hv = *(const float4*)&sh[r0 + r][k];
            acc[r][0] = fmaf(hv.x, w0.x, fmaf(hv.y, w1.x, fmaf(hv.z, w2.x, fmaf(hv.w, w3.x, acc[r][0]))));
            acc[r][1] = fmaf(hv.x, w0.y, fmaf(hv.y, w1.y, fmaf(hv.z, w2.y, fmaf(hv.w, w3.y, acc[r][1]))));
            acc[r][2] = fmaf(hv.x, w0.z, fmaf(hv.y, w1.z, fmaf(hv.z, w2.z, fmaf(hv.w, w3.z, acc[r][2]))));
            acc[r][3] = fmaf(hv.x, w0.w, fmaf(hv.y, w1.w, fmaf(hv.z, w2.w, fmaf(hv.w, w3.w, acc[r][3]))));
        }
    }

    int n0 = blockIdx.x * 32;
    float4 as = *(const float4*)&a[c0];
    float4 ad = *(const float4*)&a[64 + c0];

    #pragma unroll
    for (int r = 0; r < 2; ++r) {
        int n = n0 + r0 + r;
        __half2 p0 = __floats2half2_rn(acc[r][0], acc[r][1]);
        __half2 p1 = __floats2half2_rn(acc[r][2], acc[r][3]);
        unsigned* dstw = &g_zh[(size_t)n * 32 + (c0 >> 1)];
        dstw[0] = *(unsigned*)&p0;
        dstw[1] = *(unsigned*)&p1;
        float zs = acc[r][0] * as.x + acc[r][1] * as.y + acc[r][2] * as.z + acc[r][3] * as.w;
        float zd = acc[r][0] * ad.x + acc[r][1] * ad.y + acc[r][2] * ad.z + acc[r][3] * ad.w;
        #pragma unroll
        for (int o = 8; o > 0; o >>= 1) {
            zs += __shfl_xor_sync(0xffffffffu, zs, o);
            zd += __shfl_xor_sync(0xffffffffu, zd, o);
        }
        if (tx == 0) { g_zs[n] = zs; g_zd[n] = zd; }
    }
}

// ---------------- K2: edge pass (4 edges/thread, batched for MLP) ----------------
__global__ void k_edge(const int* __restrict__ src, const int* __restrict__ dst) {
    int i = blockIdx.x * blockDim.x + threadIdx.x;   // quad index
    if (i * 4 >= N_EDGES) return;
    int4 s4 = ((const int4*)src)[i];
    int4 d4 = ((const int4*)dst)[i];
    // phase 1: issue all 8 gathers (independent -> MLP 8)
    float zs0 = g_zs[s4.x], zd0 = g_zd[d4.x];
    float zs1 = g_zs[s4.y], zd1 = g_zd[d4.y];
    float zs2 = g_zs[s4.z], zd2 = g_zd[d4.z];
    float zs3 = g_zs[s4.w], zd3 = g_zd[d4.w];
    float w0 = __expf(zs0 + zd0);   // max-shift unnecessary (|e| < ~6)
    float w1 = __expf(zs1 + zd1);
    float w2 = __expf(zs2 + zd2);
    float w3 = __expf(zs3 + zd3);
    // phase 2: claim slots + scatter
    int p0 = atomicAdd(&g_cnt[d4.x], 1);
    int p1 = atomicAdd(&g_cnt[d4.y], 1);
    int p2 = atomicAdd(&g_cnt[d4.z], 1);
    int p3 = atomicAdd(&g_cnt[d4.w], 1);
    g_perm[d4.x * CAP + p0] = make_int2(s4.x, __float_as_int(w0));
    g_perm[d4.y * CAP + p1] = make_int2(s4.y, __float_as_int(w1));
    g_perm[d4.z * CAP + p2] = make_int2(s4.z, __float_as_int(w2));
    g_perm[d4.w * CAP + p3] = make_int2(s4.w, __float_as_int(w3));
}

// ---------------- K3: warp-per-node accumulate, 1 edge per iteration ----------------
// fp16 z row = 128B = 32 lanes x one half2 -> each lane owns 2 output columns.
// (src,w) read warp-uniform (bucket stays L1-resident). No shuffles needed.
__global__ __launch_bounds__(256) void k_accum(float* __restrict__ out) {
    int gw   = (blockIdx.x * 256 + threadIdx.x) >> 5;
    int lane = threadIdx.x & 31;
    if (gw >= N_NODES) return;
    int cnt  = g_cnt[gw];
    const int2* bucket = g_perm + (size_t)gw * CAP;
    const unsigned* z  = g_zh;

    float acc0 = 0.0f, acc1 = 0.0f, den = 0.0f;
    int j = 0;
    #pragma unroll 1
    for (; j + 4 <= cnt; j += 4) {
        int2 p0 = __ldg(&bucket[j + 0]);
        int2 p1 = __ldg(&bucket[j + 1]);
        int2 p2 = __ldg(&bucket[j + 2]);
        int2 p3 = __ldg(&bucket[j + 3]);
        unsigned u0 = __ldg(&z[p0.x * 32 + lane]);
        unsigned u1 = __ldg(&z[p1.x * 32 + lane]);
        unsigned u2 = __ldg(&z[p2.x * 32 + lane]);
        unsigned u3 = __ldg(&z[p3.x * 32 + lane]);
        float w0 = __int_as_float(p0.y), w1 = __int_as_float(p1.y);
        float w2 = __int_as_float(p2.y), w3 = __int_as_float(p3.y);
        float2 f0 = __half22float2(*(__half2*)&u0);
        float2 f1 = __half22float2(*(__half2*)&u1);
        float2 f2 = __half22float2(*(__half2*)&u2);
        float2 f3 = __half22float2(*(__half2*)&u3);
        acc0 = fmaf(w0, f0.x, acc0); acc1 = fmaf(w0, f0.y, acc1);
        acc0 = fmaf(w1, f1.x, acc0); acc1 = fmaf(w1, f1.y, acc1);
        acc0 = fmaf(w2, f2.x, acc0); acc1 = fmaf(w2, f2.y, acc1);
        acc0 = fmaf(w3, f3.x, acc0); acc1 = fmaf(w3, f3.y, acc1);
        den += (w0 + w1) + (w2 + w3);
    }
    for (; j < cnt; ++j) {
        int2 p = __ldg(&bucket[j]);
        unsigned u = __ldg(&z[p.x * 32 + lane]);
        float w = __int_as_float(p.y);
        float2 f = __half22float2(*(__half2*)&u);
        acc0 = fmaf(w, f.x, acc0); acc1 = fmaf(w, f.y, acc1);
        den += w;
    }
    float inv = (cnt > 0) ? (1.0f / den) : 0.0f;
    float2 res = make_float2(acc0 * inv, acc1 * inv);
    ((float2*)out)[(size_t)gw * 32 + lane] = res;
}

// ---------------- launch ----------------
extern "C" void kernel_launch(void* const* d_in, const int* in_sizes, int n_in,
                              void* d_out, int out_size) {
    const float* h   = (const float*)d_in[0];
    const float* W   = (const float*)d_in[1];
    const float* a   = (const float*)d_in[2];
    const int*   src = (const int*)d_in[3];
    const int*   dst = (const int*)d_in[4];
    float* out = (float*)d_out;
    (void)in_sizes; (void)n_in; (void)out_size;

    k_zero<<<(N_NODES + 255) / 256, 256>>>();
    k_gemm<<<N_NODES / 32, 256>>>(h, W, a);                    // 100000 % 32 == 0
    k_edge<<<((N_EDGES / 4) + 255) / 256, 256>>>(src, dst);    // 4 edges / thread
    k_accum<<<(N_NODES * 32 + 255) / 256, 256>>>(out);
}

// round 7
// speedup vs baseline: 1.0130x; 1.0099x over previous
#include <cuda_runtime.h>
#include <cuda_fp16.h>
#include <cstdint>

#define N_NODES 100000
#define N_EDGES 3200000
#define D_IN    128
#define D_OUT   64
#define CAP     96      // max in-degree bucket capacity (actual max ~58 for Poisson(32))

// ---------------- scratch (static device globals; no allocation) ----------------
__device__ unsigned g_zh  [(size_t)N_NODES * 32];      // z as half2 (64 cols -> 32 words), 12.8 MB
__device__ float    g_ezs [N_NODES];                   // exp(z . a[:64])
__device__ float    g_ezd [N_NODES];                   // exp(z . a[64:])
__device__ int      g_cnt [N_NODES];                   // bucket fill counts
__device__ int2     g_perm[(size_t)N_NODES * CAP];     // (src, bitcast(w)) buckets, 76.8 MB

// ---------------- K0: zero counts ----------------
__global__ void k_zero() {
    int i = blockIdx.x * blockDim.x + threadIdx.x;
    if (i < N_NODES) g_cnt[i] = 0;
}

// ---------------- K1: z = h @ W  (+ fused exp(zs)/exp(zd) epilogue, fp16 z store) ------
// block = 256 threads; tile = 32 nodes x 64 cols; thread = 2 nodes x 4 cols.
__global__ __launch_bounds__(256) void k_gemm(const float* __restrict__ h,
                                              const float* __restrict__ W,
                                              const float* __restrict__ a) {
    __shared__ float sW[D_IN][D_OUT];   // 32 KB
    __shared__ float sh[32][D_IN];      // 16 KB

    int t = threadIdx.x;
    {
        const float4* W4 = (const float4*)W;
        float4* sW4 = (float4*)sW;
        #pragma unroll
        for (int i = 0; i < 8; ++i) sW4[t + i * 256] = W4[t + i * 256];
    }
    {
        int n0 = blockIdx.x * 32;
        const float4* h4 = (const float4*)(h + (size_t)n0 * D_IN);
        float4* sh4 = (float4*)sh;
        #pragma unroll
        for (int i = 0; i < 4; ++i) sh4[t + i * 256] = h4[t + i * 256];
    }
    __syncthreads();

    int tx = t & 15;          // column group: cols c0..c0+3
    int ty = t >> 4;          // node group:   rows r0, r0+1
    int c0 = tx * 4;
    int r0 = ty * 2;

    float acc[2][4] = {};
    #pragma unroll
    for (int k = 0; k < D_IN; k += 4) {
        float4 w0 = *(const float4*)&sW[k + 0][c0];
        float4 w1 = *(const float4*)&sW[k + 1][c0];
        float4 w2 = *(const float4*)&sW[k + 2][c0];
        float4 w3 = *(const float4*)&sW[k + 3][c0];
        #pragma unroll
        for (int r = 0; r < 2; ++r) {
            float4 hv = *(const float4*)&sh[r0 + r][k];
            acc[r][0] = fmaf(hv.x, w0.x, fmaf(hv.y, w1.x, fmaf(hv.z, w2.x, fmaf(hv.w, w3.x, acc[r][0]))));
            acc[r][1] = fmaf(hv.x, w0.y, fmaf(hv.y, w1.y, fmaf(hv.z, w2.y, fmaf(hv.w, w3.y, acc[r][1]))));
            acc[r][2] = fmaf(hv.x, w0.z, fmaf(hv.y, w1.z, fmaf(hv.z, w2.z, fmaf(hv.w, w3.z, acc[r][2]))));
            acc[r][3] = fmaf(hv.x, w0.w, fmaf(hv.y, w1.w, fmaf(hv.z, w2.w, fmaf(hv.w, w3.w, acc[r][3]))));
        }
    }

    int n0 = blockIdx.x * 32;
    float4 as = *(const float4*)&a[c0];
    float4 ad = *(const float4*)&a[64 + c0];

    #pragma unroll
    for (int r = 0; r < 2; ++r) {
        int n = n0 + r0 + r;
        __half2 p0 = __floats2half2_rn(acc[r][0], acc[r][1]);
        __half2 p1 = __floats2half2_rn(acc[r][2], acc[r][3]);
        unsigned* dstw = &g_zh[(size_t)n * 32 + (c0 >> 1)];
        dstw[0] = *(unsigned*)&p0;
        dstw[1] = *(unsigned*)&p1;
        float zs = acc[r][0] * as.x + acc[r][1] * as.y + acc[r][2] * as.z + acc[r][3] * as.w;
        float zd = acc[r][0] * ad.x + acc[r][1] * ad.y + acc[r][2] * ad.z + acc[r][3] * ad.w;
        #pragma unroll
        for (int o = 8; o > 0; o >>= 1) {
            zs += __shfl_xor_sync(0xffffffffu, zs, o);
            zd += __shfl_xor_sync(0xffffffffu, zd, o);
        }
        if (tx == 0) { g_ezs[n] = __expf(zs); g_ezd[n] = __expf(zd); }
    }
}

// ---------------- K2: edge pass (4 edges/thread): w = ezs[s]*ezd[d], bucket drop -------
__global__ void k_edge(const int* __restrict__ src, const int* __restrict__ dst) {
    int i = blockIdx.x * blockDim.x + threadIdx.x;   // quad index
    if (i * 4 >= N_EDGES) return;
    int4 s4 = ((const int4*)src)[i];
    int4 d4 = ((const int4*)dst)[i];
    // phase 1: all 8 gathers in flight (MLP 8)
    float a0 = g_ezs[s4.x], b0 = g_ezd[d4.x];
    float a1 = g_ezs[s4.y], b1 = g_ezd[d4.y];
    float a2 = g_ezs[s4.z], b2 = g_ezd[d4.z];
    float a3 = g_ezs[s4.w], b3 = g_ezd[d4.w];
    float w0 = a0 * b0, w1 = a1 * b1, w2 = a2 * b2, w3 = a3 * b3;
    // phase 2: claim slots + scatter
    int p0 = atomicAdd(&g_cnt[d4.x], 1);
    int p1 = atomicAdd(&g_cnt[d4.y], 1);
    int p2 = atomicAdd(&g_cnt[d4.z], 1);
    int p3 = atomicAdd(&g_cnt[d4.w], 1);
    g_perm[d4.x * CAP + p0] = make_int2(s4.x, __float_as_int(w0));
    g_perm[d4.y * CAP + p1] = make_int2(s4.y, __float_as_int(w1));
    g_perm[d4.z * CAP + p2] = make_int2(s4.z, __float_as_int(w2));
    g_perm[d4.w * CAP + p3] = make_int2(s4.w, __float_as_int(w3));
}

// ---------------- K3: warp-per-node accumulate, lean loop -------------------------
// fp16 z row = 128B = 32 lanes x one half2 -> lane owns 2 output columns; no shfl.
// Buckets read as int4 (2 edges / LDG.128). Quad-unrolled: 4 z-gathers in flight.
__global__ __launch_bounds__(256) void k_accum(float* __restrict__ out) {
    int gw   = (blockIdx.x * 256 + threadIdx.x) >> 5;
    int lane = threadIdx.x & 31;
    if (gw >= N_NODES) return;
    int cnt  = g_cnt[gw];
    const int2* bucket = g_perm + (size_t)gw * CAP;
    const int4* b4     = (const int4*)bucket;

    float acc0 = 0.0f, acc1 = 0.0f, den = 0.0f;
    int nq = cnt >> 2;
    #pragma unroll 1
    for (int q = 0; q < nq; ++q) {
        int4 ba = b4[2 * q];          // edges 4q, 4q+1
        int4 bb = b4[2 * q + 1];      // edges 4q+2, 4q+3
        unsigned u0 = g_zh[ba.x * 32 + lane];
        unsigned u1 = g_zh[ba.z * 32 + lane];
        unsigned u2 = g_zh[bb.x * 32 + lane];
        unsigned u3 = g_zh[bb.z * 32 + lane];
        float w0 = __int_as_float(ba.y), w1 = __int_as_float(ba.w);
        float w2 = __int_as_float(bb.y), w3 = __int_as_float(bb.w);
        float2 f0 = __half22float2(*(__half2*)&u0);
        float2 f1 = __half22float2(*(__half2*)&u1);
        float2 f2 = __half22float2(*(__half2*)&u2);
        float2 f3 = __half22float2(*(__half2*)&u3);
        acc0 = fmaf(w0, f0.x, acc0); acc1 = fmaf(w0, f0.y, acc1);
        acc0 = fmaf(w1, f1.x, acc0); acc1 = fmaf(w1, f1.y, acc1);
        acc0 = fmaf(w2, f2.x, acc0); acc1 = fmaf(w2, f2.y, acc1);
        acc0 = fmaf(w3, f3.x, acc0); acc1 = fmaf(w3, f3.y, acc1);
        den += (w0 + w1) + (w2 + w3);
    }
    for (int j = nq << 2; j < cnt; ++j) {
        int2 p = bucket[j];
        unsigned u = g_zh[p.x * 32 + lane];
        float w = __int_as_float(p.y);
        float2 f = __half22float2(*(__half2*)&u);
        acc0 = fmaf(w, f.x, acc0); acc1 = fmaf(w, f.y, acc1);
        den += w;
    }
    float inv = (cnt > 0) ? (1.0f / den) : 0.0f;
    float2 res = make_float2(acc0 * inv, acc1 * inv);
    ((float2*)out)[(size_t)gw * 32 + lane] = res;
}

// ---------------- launch ----------------
extern "C" void kernel_launch(void* const* d_in, const int* in_sizes, int n_in,
                              void* d_out, int out_size) {
    const float* h   = (const float*)d_in[0];
    const float* W   = (const float*)d_in[1];
    const float* a   = (const float*)d_in[2];
    const int*   src = (const int*)d_in[3];
    const int*   dst = (const int*)d_in[4];
    float* out = (float*)d_out;
    (void)in_sizes; (void)n_in; (void)out_size;

    k_zero<<<(N_NODES + 255) / 256, 256>>>();
    k_gemm<<<N_NODES / 32, 256>>>(h, W, a);                    // 100000 % 32 == 0
    k_edge<<<((N_EDGES / 4) + 255) / 256, 256>>>(src, dst);    // 4 edges / thread
    k_accum<<<(N_NODES * 32 + 255) / 256, 256>>>(out);
}